// round 4
// baseline (speedup 1.0000x reference)
#include <cuda_runtime.h>

#define CN0 262144
#define CN1 131072
#define CN2 65536
#define CE0 2097152
#define CE1 1048576
#define CIN 128
#define CH  32
#define CEPS 1e-12f

// ---- scratch (device globals; referenced from DEVICE code only) ----
__device__ float g_y0[(size_t)CN0 * CH];    // x @ wl0^T       (32 MB)
__device__ float g_r0[(size_t)CN1 * CH];    // x[:N1] @ wr0^T  (16 MB)
__device__ float g_h [(size_t)CN1 * CH];    // layer-0 output  (16 MB)
__device__ float g_z1[(size_t)CN1 * CH];    // h @ wl1^T       (16 MB)
__device__ float g_r1[(size_t)CN2 * CH];    // h[:N2] @ wr1^T  (8 MB)

__device__ int g_cnt0[CN1];                 // per-target degree
__device__ int g_cur0[CN1];                 // bucket cursor
__device__ int g_offl0[CN1];                // tile-local exclusive offsets
__device__ int g_part0[CN1 / 1024];         // per-tile totals -> exclusive
__device__ int g_eid0[CE0];                 // src ids grouped by target

__device__ int g_cnt1[CN2];
__device__ int g_cur1[CN2];
__device__ int g_offl1[CN2];
__device__ int g_part1[CN2 / 1024];
__device__ int g_eid1[CE1];

// ============================================================
// proj0: per-warp 4 rows. y0 = x@wl0^T (+ r0 = x@wr0^T and zero
// cnt/cur for layer-0 when DO_R). Weights transposed in smem.
// ============================================================
template <bool DO_R>
__global__ __launch_bounds__(256) void proj0_kernel(
    const float* __restrict__ x,
    const float* __restrict__ wl0,
    const float* __restrict__ wr0,
    int row_base)
{
    __shared__ float swl[CIN * CH];   // [k][j]
    __shared__ float swr[CIN * CH];
    int tid = threadIdx.x;
    #pragma unroll
    for (int idx = tid; idx < CIN * CH; idx += 256) {
        int j = idx >> 7, k = idx & 127;
        swl[k * CH + j] = wl0[idx];
        if (DO_R) swr[k * CH + j] = wr0[idx];
    }
    __syncthreads();

    int lane = tid & 31;
    int warp = blockIdx.x * 8 + (tid >> 5);
    int rb = row_base + warp * 4;

    const float4* x4 = (const float4*)x;
    size_t b0 = (size_t)rb * 32;

    float al[4] = {0.f, 0.f, 0.f, 0.f};
    float ar[4] = {0.f, 0.f, 0.f, 0.f};

    #pragma unroll 4
    for (int k4 = 0; k4 < 32; k4++) {
        float4 v[4];
        #pragma unroll
        for (int i = 0; i < 4; i++) v[i] = __ldg(&x4[b0 + (size_t)i * 32 + k4]);
        int kb = k4 * 4;
        float wlr[4], wrr[4];
        #pragma unroll
        for (int d = 0; d < 4; d++) {
            wlr[d] = swl[(kb + d) * CH + lane];
            if (DO_R) wrr[d] = swr[(kb + d) * CH + lane];
        }
        #pragma unroll
        for (int i = 0; i < 4; i++) {
            al[i] = fmaf(v[i].x, wlr[0], al[i]);
            al[i] = fmaf(v[i].y, wlr[1], al[i]);
            al[i] = fmaf(v[i].z, wlr[2], al[i]);
            al[i] = fmaf(v[i].w, wlr[3], al[i]);
            if (DO_R) {
                ar[i] = fmaf(v[i].x, wrr[0], ar[i]);
                ar[i] = fmaf(v[i].y, wrr[1], ar[i]);
                ar[i] = fmaf(v[i].z, wrr[2], ar[i]);
                ar[i] = fmaf(v[i].w, wrr[3], ar[i]);
            }
        }
    }

    #pragma unroll
    for (int i = 0; i < 4; i++) {
        int r = rb + i;
        g_y0[(size_t)r * CH + lane] = al[i];
        if (DO_R) g_r0[(size_t)r * CH + lane] = ar[i];
    }
    if (DO_R && lane < 4) {        // zero layer-0 hist state
        g_cnt0[rb + lane] = 0;
        g_cur0[rb + lane] = 0;
    }
}

// ============================================================
// hist: 4 edges/thread, int atomics on degree counters.
// ============================================================
template <int LAYER>
__global__ __launch_bounds__(256) void hist_kernel(const int* __restrict__ tgt)
{
    int* cnt = (LAYER == 0) ? g_cnt0 : g_cnt1;
    int b = (blockIdx.x * 256 + threadIdx.x) * 4;
    int4 t = __ldg((const int4*)(tgt + b));
    atomicAdd(&cnt[t.x], 1);
    atomicAdd(&cnt[t.y], 1);
    atomicAdd(&cnt[t.z], 1);
    atomicAdd(&cnt[t.w], 1);
}

// ============================================================
// scanA: per 1024-tile exclusive scan of counts; tile total -> part.
// ============================================================
template <int LAYER>
__global__ __launch_bounds__(256) void scanA_kernel()
{
    const int* cnt = (LAYER == 0) ? g_cnt0 : g_cnt1;
    int* offl = (LAYER == 0) ? g_offl0 : g_offl1;
    int* part = (LAYER == 0) ? g_part0 : g_part1;

    __shared__ int wsum[8];
    int tid = threadIdx.x;
    int base = blockIdx.x * 1024 + tid * 4;
    int4 c = __ldg((const int4*)(cnt + base));
    int s1 = c.x + c.y, s2 = s1 + c.z, s3 = s2 + c.w;

    int lane = tid & 31, w = tid >> 5;
    int v = s3;
    #pragma unroll
    for (int o = 1; o < 32; o <<= 1) {
        int t = __shfl_up_sync(0xffffffffu, v, o);
        if (lane >= o) v += t;
    }
    int thr_excl = v - s3;
    if (lane == 31) wsum[w] = v;
    __syncthreads();
    if (w == 0) {
        int ws = (lane < 8) ? wsum[lane] : 0;
        #pragma unroll
        for (int o = 1; o < 8; o <<= 1) {
            int t = __shfl_up_sync(0xffffffffu, ws, o);
            if (lane >= o) ws += t;
        }
        if (lane < 8) wsum[lane] = ws;   // inclusive warp sums
    }
    __syncthreads();
    int wexcl = (w == 0) ? 0 : wsum[w - 1];
    int e = wexcl + thr_excl;

    int4 o4;
    o4.x = e;
    o4.y = e + c.x;
    o4.z = e + s1;
    o4.w = e + s2;
    *(int4*)(offl + base) = o4;
    if (tid == 255) part[blockIdx.x] = wsum[7];
}

// ============================================================
// scanB: exclusive scan of tile totals (n <= 128), one block.
// ============================================================
template <int LAYER>
__global__ __launch_bounds__(128) void scanB_kernel()
{
    int* part = (LAYER == 0) ? g_part0 : g_part1;
    const int n = (LAYER == 0) ? (CN1 / 1024) : (CN2 / 1024);

    __shared__ int ws[4];
    int tid = threadIdx.x;
    int v = (tid < n) ? part[tid] : 0;
    int lane = tid & 31, w = tid >> 5;
    int x = v;
    #pragma unroll
    for (int o = 1; o < 32; o <<= 1) {
        int t = __shfl_up_sync(0xffffffffu, x, o);
        if (lane >= o) x += t;
    }
    if (lane == 31) ws[w] = x;
    __syncthreads();
    if (tid == 0) {
        int a = 0;
        #pragma unroll
        for (int i = 0; i < 4; i++) { int t = ws[i]; ws[i] = a; a += t; }
    }
    __syncthreads();
    if (tid < n) part[tid] = (x - v) + ws[w];   // exclusive
}

// ============================================================
// bucket: 4 edges/thread; pos = off(t) + cur(t)++; eid[pos] = src.
// ============================================================
template <int LAYER>
__global__ __launch_bounds__(256) void bucket_kernel(
    const int* __restrict__ src, const int* __restrict__ tgt)
{
    const int* offl = (LAYER == 0) ? g_offl0 : g_offl1;
    const int* part = (LAYER == 0) ? g_part0 : g_part1;
    int* cur = (LAYER == 0) ? g_cur0 : g_cur1;
    int* eid = (LAYER == 0) ? g_eid0 : g_eid1;

    int b = (blockIdx.x * 256 + threadIdx.x) * 4;
    int4 t = __ldg((const int4*)(tgt + b));
    int4 s = __ldg((const int4*)(src + b));
    #pragma unroll
    for (int i = 0; i < 4; i++) {
        int ti = (i == 0) ? t.x : (i == 1) ? t.y : (i == 2) ? t.z : t.w;
        int si = (i == 0) ? s.x : (i == 1) ? s.y : (i == 2) ? s.z : s.w;
        int off = __ldg(offl + ti) + __ldg(part + (ti >> 10));
        int pos = off + atomicAdd(&cur[ti], 1);
        eid[pos] = si;
    }
}

// ============================================================
// aggfin: 8 threads/target. Register-accumulate neighbor rows,
// then fused mean + bias + root + L2norm (+relu for layer 0).
// ============================================================
template <int LAYER>
__global__ __launch_bounds__(256) void aggfin_kernel(
    const float* __restrict__ bias, float* __restrict__ out_param)
{
    const float* table = (LAYER == 0) ? g_y0 : g_z1;
    const float* rt    = (LAYER == 0) ? g_r0 : g_r1;
    const int*   cnta  = (LAYER == 0) ? g_cnt0 : g_cnt1;
    const int*   offl  = (LAYER == 0) ? g_offl0 : g_offl1;
    const int*   part  = (LAYER == 0) ? g_part0 : g_part1;
    const int*   eid   = (LAYER == 0) ? g_eid0 : g_eid1;
    float*       out   = (LAYER == 0) ? g_h : out_param;

    int tid = blockIdx.x * 256 + threadIdx.x;
    int row = tid >> 3;
    int f4 = tid & 7;

    int cnt = __ldg(cnta + row);
    int start = __ldg(offl + row) + __ldg(part + (row >> 10));

    float4 acc = make_float4(0.f, 0.f, 0.f, 0.f);
    int i = 0;
    for (; i + 2 <= cnt; i += 2) {
        int s0 = __ldg(eid + start + i);
        int s1 = __ldg(eid + start + i + 1);
        float4 v0 = __ldg((const float4*)(table + (size_t)s0 * CH) + f4);
        float4 v1 = __ldg((const float4*)(table + (size_t)s1 * CH) + f4);
        acc.x += v0.x + v1.x; acc.y += v0.y + v1.y;
        acc.z += v0.z + v1.z; acc.w += v0.w + v1.w;
    }
    if (i < cnt) {
        int s0 = __ldg(eid + start + i);
        float4 v0 = __ldg((const float4*)(table + (size_t)s0 * CH) + f4);
        acc.x += v0.x; acc.y += v0.y; acc.z += v0.z; acc.w += v0.w;
    }

    float inv = 1.f / (float)max(cnt, 1);
    float4 b = __ldg((const float4*)bias + f4);
    float4 r = __ldg((const float4*)(rt + (size_t)row * CH) + f4);

    float4 v;
    v.x = fmaf(acc.x, inv, b.x) + r.x;
    v.y = fmaf(acc.y, inv, b.y) + r.y;
    v.z = fmaf(acc.z, inv, b.z) + r.z;
    v.w = fmaf(acc.w, inv, b.w) + r.w;

    float s = v.x * v.x + v.y * v.y + v.z * v.z + v.w * v.w;
    s += __shfl_xor_sync(0xffffffffu, s, 1);
    s += __shfl_xor_sync(0xffffffffu, s, 2);
    s += __shfl_xor_sync(0xffffffffu, s, 4);
    float rinv = 1.f / fmaxf(sqrtf(s), CEPS);

    float4 o;
    o.x = v.x * rinv; o.y = v.y * rinv; o.z = v.z * rinv; o.w = v.w * rinv;
    if (LAYER == 0) {
        o.x = fmaxf(o.x, 0.f); o.y = fmaxf(o.y, 0.f);
        o.z = fmaxf(o.z, 0.f); o.w = fmaxf(o.w, 0.f);
    }
    ((float4*)(out + (size_t)row * CH))[f4] = o;
}

// ============================================================
// proj1: z1 = h@wl1^T (all N1), r1 = h[:N2]@wr1^T, zero cnt1/cur1.
// ============================================================
__global__ __launch_bounds__(256) void proj1_kernel(
    const float* __restrict__ wl1, const float* __restrict__ wr1)
{
    __shared__ float swl[CH * CH];
    __shared__ float swr[CH * CH];
    int tid = threadIdx.x;
    for (int idx = tid; idx < CH * CH; idx += 256) {
        int j = idx >> 5, k = idx & 31;
        swl[k * CH + j] = wl1[idx];
        swr[k * CH + j] = wr1[idx];
    }
    __syncthreads();

    int lane = tid & 31;
    int warp = blockIdx.x * 8 + (tid >> 5);
    int rb = warp * 4;

    const float4* h4 = (const float4*)g_h;
    size_t b0 = (size_t)rb * 8;

    float al[4] = {0.f, 0.f, 0.f, 0.f};
    float ar[4] = {0.f, 0.f, 0.f, 0.f};

    #pragma unroll
    for (int k4 = 0; k4 < 8; k4++) {
        float4 v[4];
        #pragma unroll
        for (int i = 0; i < 4; i++) v[i] = h4[b0 + (size_t)i * 8 + k4];
        int kb = k4 * 4;
        float wlr[4], wrr[4];
        #pragma unroll
        for (int d = 0; d < 4; d++) {
            wlr[d] = swl[(kb + d) * CH + lane];
            wrr[d] = swr[(kb + d) * CH + lane];
        }
        #pragma unroll
        for (int i = 0; i < 4; i++) {
            al[i] = fmaf(v[i].x, wlr[0], al[i]);
            al[i] = fmaf(v[i].y, wlr[1], al[i]);
            al[i] = fmaf(v[i].z, wlr[2], al[i]);
            al[i] = fmaf(v[i].w, wlr[3], al[i]);
            ar[i] = fmaf(v[i].x, wrr[0], ar[i]);
            ar[i] = fmaf(v[i].y, wrr[1], ar[i]);
            ar[i] = fmaf(v[i].z, wrr[2], ar[i]);
            ar[i] = fmaf(v[i].w, wrr[3], ar[i]);
        }
    }

    #pragma unroll
    for (int i = 0; i < 4; i++) {
        int r = rb + i;
        g_z1[(size_t)r * CH + lane] = al[i];
        if (r < CN2) g_r1[(size_t)r * CH + lane] = ar[i];
    }
    if (rb < CN2 && lane < 4) {
        g_cnt1[rb + lane] = 0;
        g_cur1[rb + lane] = 0;
    }
}

// ============================================================
extern "C" void kernel_launch(void* const* d_in, const int* in_sizes, int n_in,
                              void* d_out, int out_size)
{
    const float* x    = (const float*)d_in[0];
    const int*   src0 = (const int*)d_in[1];
    const int*   tgt0 = (const int*)d_in[2];
    const int*   src1 = (const int*)d_in[3];
    const int*   tgt1 = (const int*)d_in[4];
    const float* wl0  = (const float*)d_in[5];
    const float* bl0  = (const float*)d_in[6];
    const float* wr0  = (const float*)d_in[7];
    const float* wl1  = (const float*)d_in[8];
    const float* bl1  = (const float*)d_in[9];
    const float* wr1  = (const float*)d_in[10];
    float* out = (float*)d_out;

    // layer 0
    proj0_kernel<true ><<<CN1 / 32, 256>>>(x, wl0, wr0, 0);          // also zeroes cnt0/cur0
    proj0_kernel<false><<<(CN0 - CN1) / 32, 256>>>(x, wl0, wr0, CN1);
    hist_kernel<0><<<CE0 / 1024, 256>>>(tgt0);
    scanA_kernel<0><<<CN1 / 1024, 256>>>();
    scanB_kernel<0><<<1, 128>>>();
    bucket_kernel<0><<<CE0 / 1024, 256>>>(src0, tgt0);
    aggfin_kernel<0><<<CN1 * 8 / 256, 256>>>(bl0, nullptr);

    // layer 1
    proj1_kernel<<<CN1 / 32, 256>>>(wl1, wr1);                       // also zeroes cnt1/cur1
    hist_kernel<1><<<CE1 / 1024, 256>>>(tgt1);
    scanA_kernel<1><<<CN2 / 1024, 256>>>();
    scanB_kernel<1><<<1, 128>>>();
    bucket_kernel<1><<<CE1 / 1024, 256>>>(src1, tgt1);
    aggfin_kernel<1><<<CN2 * 8 / 256, 256>>>(bl1, out);
}

// round 5
// speedup vs baseline: 1.0954x; 1.0954x over previous
#include <cuda_runtime.h>

#define CN0 262144
#define CN1 131072
#define CN2 65536
#define CE0 2097152
#define CE1 1048576
#define CIN 128
#define CH  32
#define CEPS 1e-12f

typedef unsigned long long u64;

// ---- scratch (device globals; referenced from DEVICE code only) ----
__device__ float g_y0[(size_t)CN0 * CH];    // x @ wl0^T       (32 MB)
__device__ float g_r0[(size_t)CN1 * CH];    // x[:N1] @ wr0^T  (16 MB)
__device__ float g_h [(size_t)CN1 * CH];    // layer-0 output  (16 MB)
__device__ float g_z1[(size_t)CN1 * CH];    // h @ wl1^T       (16 MB)
__device__ float g_r1[(size_t)CN2 * CH];    // h[:N2] @ wr1^T  (8 MB)

__device__ int g_cnt0[CN1];                 // per-target degree
__device__ int g_cur0[CN1];                 // bucket cursor (start -> end)
__device__ int g_offl0[CN1];                // tile-local exclusive offsets
__device__ int g_part0[CN1 / 1024];         // per-tile totals -> exclusive
__device__ int g_eid0[CE0];                 // src ids grouped by target

__device__ int g_cnt1[CN2];
__device__ int g_cur1[CN2];
__device__ int g_offl1[CN2];
__device__ int g_part1[CN2 / 1024];
__device__ int g_eid1[CE1];

__device__ __forceinline__ u64 fma2(u64 a, u64 b, u64 c) {
    u64 d;
    asm("fma.rn.f32x2 %0, %1, %2, %3;" : "=l"(d) : "l"(a), "l"(b), "l"(c));
    return d;
}
__device__ __forceinline__ u64 packf2(float lo, float hi) {
    u64 u;
    asm("mov.b64 %0, {%1,%2};" : "=l"(u) : "f"(lo), "f"(hi));
    return u;
}
__device__ __forceinline__ float sumf2(u64 u) {
    float lo, hi;
    asm("mov.b64 {%0,%1}, %2;" : "=f"(lo), "=f"(hi) : "l"(u));
    return lo + hi;
}

// ============================================================
// zero: cnt0 and cnt1 -> 0 (int4 stores)
// ============================================================
__global__ __launch_bounds__(256) void zero_kernel()
{
    int t = blockIdx.x * 256 + threadIdx.x;          // 49152 int4 slots
    const int4 z = make_int4(0, 0, 0, 0);
    if (t < CN1 / 4) ((int4*)g_cnt0)[t] = z;
    else             ((int4*)g_cnt1)[t - CN1 / 4] = z;
}

// ============================================================
// proj0: per-warp 4 rows via packed f32x2 FMA over K-pairs.
// y0 = x@wl0^T (+ r0 = x@wr0^T when DO_R). Weights pre-packed
// {w[k],w[k+1]} per output lane in smem.
// ============================================================
template <bool DO_R>
__global__ __launch_bounds__(256) void proj0_kernel(
    const float* __restrict__ x,
    const float* __restrict__ wl0,
    const float* __restrict__ wr0,
    int row_base)
{
    __shared__ u64 swl[(CIN / 2) * CH];   // [kp][j]
    __shared__ u64 swr[(CIN / 2) * CH];
    int tid = threadIdx.x;
    // stage: float4 chunk c -> j = c>>5, k4 = c&31 -> two packed pairs
    #pragma unroll
    for (int c = tid; c < CH * (CIN / 4); c += 256) {
        int j = c >> 5, k4 = c & 31;
        float4 w = __ldg((const float4*)wl0 + c);
        swl[(k4 * 2 + 0) * CH + j] = packf2(w.x, w.y);
        swl[(k4 * 2 + 1) * CH + j] = packf2(w.z, w.w);
        if (DO_R) {
            float4 v = __ldg((const float4*)wr0 + c);
            swr[(k4 * 2 + 0) * CH + j] = packf2(v.x, v.y);
            swr[(k4 * 2 + 1) * CH + j] = packf2(v.z, v.w);
        }
    }
    __syncthreads();

    int lane = tid & 31;
    int warp = blockIdx.x * 8 + (tid >> 5);
    int rb = row_base + warp * 4;

    const ulonglong2* x2 = (const ulonglong2*)x;     // 16B chunks = 2 k-pairs
    size_t b0 = (size_t)rb * 32;                     // ulonglong2 idx of row rb

    u64 accl[4] = {0ull, 0ull, 0ull, 0ull};
    u64 accr[4] = {0ull, 0ull, 0ull, 0ull};

    #pragma unroll 4
    for (int k4 = 0; k4 < 32; k4++) {
        ulonglong2 v[4];
        #pragma unroll
        for (int i = 0; i < 4; i++) v[i] = __ldg(&x2[b0 + (size_t)i * 32 + k4]);
        u64 wl_lo = swl[(2 * k4 + 0) * CH + lane];
        u64 wl_hi = swl[(2 * k4 + 1) * CH + lane];
        u64 wr_lo = 0, wr_hi = 0;
        if (DO_R) {
            wr_lo = swr[(2 * k4 + 0) * CH + lane];
            wr_hi = swr[(2 * k4 + 1) * CH + lane];
        }
        #pragma unroll
        for (int i = 0; i < 4; i++) {
            accl[i] = fma2(v[i].x, wl_lo, accl[i]);
            accl[i] = fma2(v[i].y, wl_hi, accl[i]);
            if (DO_R) {
                accr[i] = fma2(v[i].x, wr_lo, accr[i]);
                accr[i] = fma2(v[i].y, wr_hi, accr[i]);
            }
        }
    }

    #pragma unroll
    for (int i = 0; i < 4; i++) {
        int r = rb + i;
        g_y0[(size_t)r * CH + lane] = sumf2(accl[i]);
        if (DO_R) g_r0[(size_t)r * CH + lane] = sumf2(accr[i]);
    }
}

// ============================================================
// hist: 4 edges/thread, int atomics on degree counters.
// ============================================================
template <int LAYER>
__global__ __launch_bounds__(256) void hist_kernel(const int* __restrict__ tgt)
{
    int* cnt = (LAYER == 0) ? g_cnt0 : g_cnt1;
    int b = (blockIdx.x * 256 + threadIdx.x) * 4;
    int4 t = __ldg((const int4*)(tgt + b));
    atomicAdd(&cnt[t.x], 1);
    atomicAdd(&cnt[t.y], 1);
    atomicAdd(&cnt[t.z], 1);
    atomicAdd(&cnt[t.w], 1);
}

// ============================================================
// scanA: per 1024-tile exclusive scan of counts; tile total -> part.
// ============================================================
template <int LAYER>
__global__ __launch_bounds__(256) void scanA_kernel()
{
    const int* cnt = (LAYER == 0) ? g_cnt0 : g_cnt1;
    int* offl = (LAYER == 0) ? g_offl0 : g_offl1;
    int* part = (LAYER == 0) ? g_part0 : g_part1;

    __shared__ int wsum[8];
    int tid = threadIdx.x;
    int base = blockIdx.x * 1024 + tid * 4;
    int4 c = __ldg((const int4*)(cnt + base));
    int s1 = c.x + c.y, s2 = s1 + c.z, s3 = s2 + c.w;

    int lane = tid & 31, w = tid >> 5;
    int v = s3;
    #pragma unroll
    for (int o = 1; o < 32; o <<= 1) {
        int t = __shfl_up_sync(0xffffffffu, v, o);
        if (lane >= o) v += t;
    }
    int thr_excl = v - s3;
    if (lane == 31) wsum[w] = v;
    __syncthreads();
    if (w == 0) {
        int ws = (lane < 8) ? wsum[lane] : 0;
        #pragma unroll
        for (int o = 1; o < 8; o <<= 1) {
            int t = __shfl_up_sync(0xffffffffu, ws, o);
            if (lane >= o) ws += t;
        }
        if (lane < 8) wsum[lane] = ws;   // inclusive warp sums
    }
    __syncthreads();
    int wexcl = (w == 0) ? 0 : wsum[w - 1];
    int e = wexcl + thr_excl;

    int4 o4;
    o4.x = e;
    o4.y = e + c.x;
    o4.z = e + s1;
    o4.w = e + s2;
    *(int4*)(offl + base) = o4;
    if (tid == 255) part[blockIdx.x] = wsum[7];
}

// ============================================================
// scanB: exclusive scan of tile totals (n <= 128), one block.
// ============================================================
template <int LAYER>
__global__ __launch_bounds__(128) void scanB_kernel()
{
    int* part = (LAYER == 0) ? g_part0 : g_part1;
    const int n = (LAYER == 0) ? (CN1 / 1024) : (CN2 / 1024);

    __shared__ int ws[4];
    int tid = threadIdx.x;
    int v = (tid < n) ? part[tid] : 0;
    int lane = tid & 31, w = tid >> 5;
    int x = v;
    #pragma unroll
    for (int o = 1; o < 32; o <<= 1) {
        int t = __shfl_up_sync(0xffffffffu, x, o);
        if (lane >= o) x += t;
    }
    if (lane == 31) ws[w] = x;
    __syncthreads();
    if (tid == 0) {
        int a = 0;
        #pragma unroll
        for (int i = 0; i < 4; i++) { int t = ws[i]; ws[i] = a; a += t; }
    }
    __syncthreads();
    if (tid < n) part[tid] = (x - v) + ws[w];   // exclusive
}

// ============================================================
// initcur: cur[i] = global start offset
// ============================================================
template <int LAYER>
__global__ __launch_bounds__(256) void initcur_kernel()
{
    const int* offl = (LAYER == 0) ? g_offl0 : g_offl1;
    const int* part = (LAYER == 0) ? g_part0 : g_part1;
    int* cur = (LAYER == 0) ? g_cur0 : g_cur1;
    int i = blockIdx.x * 256 + threadIdx.x;
    cur[i] = offl[i] + part[i >> 10];
}

// ============================================================
// bucket: 4 edges/thread; pos = cur(t)++; eid[pos] = src.
// ============================================================
template <int LAYER>
__global__ __launch_bounds__(256) void bucket_kernel(
    const int* __restrict__ src, const int* __restrict__ tgt)
{
    int* cur = (LAYER == 0) ? g_cur0 : g_cur1;
    int* eid = (LAYER == 0) ? g_eid0 : g_eid1;

    int b = (blockIdx.x * 256 + threadIdx.x) * 4;
    int4 t = __ldg((const int4*)(tgt + b));
    int4 s = __ldg((const int4*)(src + b));
    #pragma unroll
    for (int i = 0; i < 4; i++) {
        int ti = (i == 0) ? t.x : (i == 1) ? t.y : (i == 2) ? t.z : t.w;
        int si = (i == 0) ? s.x : (i == 1) ? s.y : (i == 2) ? s.z : s.w;
        int pos = atomicAdd(&cur[ti], 1);
        eid[pos] = si;
    }
}

// ============================================================
// aggfin: ONE WARP per target row. lane = (slot g in 0..3, f4 in 0..7).
// 4 neighbors gathered concurrently; shfl-reduce across slots; fused
// mean + bias + root + L2norm (+relu for layer 0).
// ============================================================
template <int LAYER>
__global__ __launch_bounds__(256) void aggfin_kernel(
    const float* __restrict__ bias, float* __restrict__ out_param)
{
    const float* table = (LAYER == 0) ? g_y0 : g_z1;
    const float* rt    = (LAYER == 0) ? g_r0 : g_r1;
    const int*   cnta  = (LAYER == 0) ? g_cnt0 : g_cnt1;
    const int*   cura  = (LAYER == 0) ? g_cur0 : g_cur1;   // = end offset
    const int*   eid   = (LAYER == 0) ? g_eid0 : g_eid1;
    float*       out   = (LAYER == 0) ? g_h : out_param;

    int lane = threadIdx.x & 31;
    int row = blockIdx.x * 8 + (threadIdx.x >> 5);
    int g = lane >> 3;
    int f4 = lane & 7;

    int cnt = __ldg(cnta + row);
    int start = __ldg(cura + row) - cnt;

    float4 acc = make_float4(0.f, 0.f, 0.f, 0.f);
    for (int i = g; i < cnt; i += 4) {
        int s = __ldg(eid + start + i);
        float4 v = __ldg((const float4*)(table + (size_t)s * CH) + f4);
        acc.x += v.x; acc.y += v.y; acc.z += v.z; acc.w += v.w;
    }
    // reduce across the 4 slots (xor 8, 16): every lane ends with full sum
    #pragma unroll
    for (int o = 8; o <= 16; o <<= 1) {
        acc.x += __shfl_xor_sync(0xffffffffu, acc.x, o);
        acc.y += __shfl_xor_sync(0xffffffffu, acc.y, o);
        acc.z += __shfl_xor_sync(0xffffffffu, acc.z, o);
        acc.w += __shfl_xor_sync(0xffffffffu, acc.w, o);
    }

    float inv = 1.f / (float)max(cnt, 1);
    float4 b = __ldg((const float4*)bias + f4);
    float4 r = __ldg((const float4*)(rt + (size_t)row * CH) + f4);

    float4 v;
    v.x = fmaf(acc.x, inv, b.x) + r.x;
    v.y = fmaf(acc.y, inv, b.y) + r.y;
    v.z = fmaf(acc.z, inv, b.z) + r.z;
    v.w = fmaf(acc.w, inv, b.w) + r.w;

    float s = v.x * v.x + v.y * v.y + v.z * v.z + v.w * v.w;
    s += __shfl_xor_sync(0xffffffffu, s, 1);
    s += __shfl_xor_sync(0xffffffffu, s, 2);
    s += __shfl_xor_sync(0xffffffffu, s, 4);
    float rinv = 1.f / fmaxf(sqrtf(s), CEPS);

    float4 o;
    o.x = v.x * rinv; o.y = v.y * rinv; o.z = v.z * rinv; o.w = v.w * rinv;
    if (LAYER == 0) {
        o.x = fmaxf(o.x, 0.f); o.y = fmaxf(o.y, 0.f);
        o.z = fmaxf(o.z, 0.f); o.w = fmaxf(o.w, 0.f);
    }
    if (g == 0)
        ((float4*)(out + (size_t)row * CH))[f4] = o;
}

// ============================================================
// proj1: z1 = h@wl1^T (all N1), r1 = h[:N2]@wr1^T.
// ============================================================
__global__ __launch_bounds__(256) void proj1_kernel(
    const float* __restrict__ wl1, const float* __restrict__ wr1)
{
    __shared__ float swl[CH * CH];
    __shared__ float swr[CH * CH];
    int tid = threadIdx.x;
    for (int idx = tid; idx < CH * CH; idx += 256) {
        int j = idx >> 5, k = idx & 31;
        swl[k * CH + j] = wl1[idx];
        swr[k * CH + j] = wr1[idx];
    }
    __syncthreads();

    int lane = tid & 31;
    int warp = blockIdx.x * 8 + (tid >> 5);
    int rb = warp * 4;

    const float4* h4 = (const float4*)g_h;
    size_t b0 = (size_t)rb * 8;

    float al[4] = {0.f, 0.f, 0.f, 0.f};
    float ar[4] = {0.f, 0.f, 0.f, 0.f};

    #pragma unroll
    for (int k4 = 0; k4 < 8; k4++) {
        float4 v[4];
        #pragma unroll
        for (int i = 0; i < 4; i++) v[i] = h4[b0 + (size_t)i * 8 + k4];
        int kb = k4 * 4;
        float wlr[4], wrr[4];
        #pragma unroll
        for (int d = 0; d < 4; d++) {
            wlr[d] = swl[(kb + d) * CH + lane];
            wrr[d] = swr[(kb + d) * CH + lane];
        }
        #pragma unroll
        for (int i = 0; i < 4; i++) {
            al[i] = fmaf(v[i].x, wlr[0], al[i]);
            al[i] = fmaf(v[i].y, wlr[1], al[i]);
            al[i] = fmaf(v[i].z, wlr[2], al[i]);
            al[i] = fmaf(v[i].w, wlr[3], al[i]);
            ar[i] = fmaf(v[i].x, wrr[0], ar[i]);
            ar[i] = fmaf(v[i].y, wrr[1], ar[i]);
            ar[i] = fmaf(v[i].z, wrr[2], ar[i]);
            ar[i] = fmaf(v[i].w, wrr[3], ar[i]);
        }
    }

    #pragma unroll
    for (int i = 0; i < 4; i++) {
        int r = rb + i;
        g_z1[(size_t)r * CH + lane] = al[i];
        if (r < CN2) g_r1[(size_t)r * CH + lane] = ar[i];
    }
}

// ============================================================
extern "C" void kernel_launch(void* const* d_in, const int* in_sizes, int n_in,
                              void* d_out, int out_size)
{
    const float* x    = (const float*)d_in[0];
    const int*   src0 = (const int*)d_in[1];
    const int*   tgt0 = (const int*)d_in[2];
    const int*   src1 = (const int*)d_in[3];
    const int*   tgt1 = (const int*)d_in[4];
    const float* wl0  = (const float*)d_in[5];
    const float* bl0  = (const float*)d_in[6];
    const float* wr0  = (const float*)d_in[7];
    const float* wl1  = (const float*)d_in[8];
    const float* bl1  = (const float*)d_in[9];
    const float* wr1  = (const float*)d_in[10];
    float* out = (float*)d_out;

    zero_kernel<<<(CN1 / 4 + CN2 / 4) / 256, 256>>>();          // 0
    hist_kernel<0><<<CE0 / 1024, 256>>>(tgt0);                  // 1
    scanA_kernel<0><<<CN1 / 1024, 256>>>();                     // 2
    proj0_kernel<true ><<<CN1 / 32, 256>>>(x, wl0, wr0, 0);     // 3  <- ncu capture
    proj0_kernel<false><<<(CN0 - CN1) / 32, 256>>>(x, wl0, wr0, CN1); // 4
    scanB_kernel<0><<<1, 128>>>();                              // 5
    initcur_kernel<0><<<CN1 / 256, 256>>>();                    // 6
    bucket_kernel<0><<<CE0 / 1024, 256>>>(src0, tgt0);          // 7
    hist_kernel<1><<<CE1 / 1024, 256>>>(tgt1);                  // 8
    scanA_kernel<1><<<CN2 / 1024, 256>>>();                     // 9
    scanB_kernel<1><<<1, 128>>>();                              // 10
    initcur_kernel<1><<<CN2 / 256, 256>>>();                    // 11
    bucket_kernel<1><<<CE1 / 1024, 256>>>(src1, tgt1);          // 12
    aggfin_kernel<0><<<CN1 / 8, 256>>>(bl0, nullptr);           // 13
    proj1_kernel<<<CN1 / 32, 256>>>(wl1, wr1);                  // 14
    aggfin_kernel<1><<<CN2 / 8, 256>>>(bl1, out);               // 15
}

// round 7
// speedup vs baseline: 1.9731x; 1.8012x over previous
#include <cuda_runtime.h>
#include <cuda_bf16.h>

#define CN0 262144
#define CN1 131072
#define CN2 65536
#define CE0 2097152
#define CE1 1048576
#define CIN 128
#define CH  32
#define CEPS 1e-12f

typedef unsigned int uint;

// ---- scratch (device globals; referenced from DEVICE code only) ----
__device__ float g_y0[(size_t)CN0 * CH];    // x @ wl0^T       (32 MB)
__device__ float g_r0[(size_t)CN1 * CH];    // x[:N1] @ wr0^T  (16 MB)
__device__ float g_h [(size_t)CN1 * CH];    // layer-0 output  (16 MB)
__device__ float g_z1[(size_t)CN1 * CH];    // h @ wl1^T       (16 MB)
__device__ float g_r1[(size_t)CN2 * CH];    // h[:N2] @ wr1^T  (8 MB)

__device__ __nv_bfloat16 g_whi[64 * CIN];   // [wl0;wr0] bf16 hi
__device__ __nv_bfloat16 g_wlo[64 * CIN];   // residual lo

__device__ int g_cnt0[CN1];
__device__ int g_cur0[CN1];
__device__ int g_offl0[CN1];
__device__ int g_part0[CN1 / 1024];
__device__ int g_eid0[CE0];

__device__ int g_cnt1[CN2];
__device__ int g_cur1[CN2];
__device__ int g_offl1[CN2];
__device__ int g_part1[CN2 / 1024];
__device__ int g_eid1[CE1];

__device__ __forceinline__ uint pkbf(float a, float b) {
    __nv_bfloat162 t = __halves2bfloat162(__float2bfloat16(a), __float2bfloat16(b));
    return *reinterpret_cast<uint*>(&t);
}
__device__ __forceinline__ void mma_bf16(float* d, const uint* a, uint b0, uint b1) {
    asm volatile(
        "mma.sync.aligned.m16n8k16.row.col.f32.bf16.bf16.f32 "
        "{%0,%1,%2,%3}, {%4,%5,%6,%7}, {%8,%9}, {%0,%1,%2,%3};"
        : "+f"(d[0]), "+f"(d[1]), "+f"(d[2]), "+f"(d[3])
        : "r"(a[0]), "r"(a[1]), "r"(a[2]), "r"(a[3]), "r"(b0), "r"(b1));
}

// ============================================================
// prep_w: split [wl0;wr0] (64x128 f32) into bf16 hi + residual lo.
// ============================================================
__global__ __launch_bounds__(256) void prep_w_kernel(
    const float* __restrict__ wl0, const float* __restrict__ wr0)
{
    int i = blockIdx.x * 256 + threadIdx.x;      // 8192 total
    float v = (i < 32 * CIN) ? wl0[i] : wr0[i - 32 * CIN];
    __nv_bfloat16 h = __float2bfloat16(v);
    g_whi[i] = h;
    g_wlo[i] = __float2bfloat16(v - __bfloat162float(h));
}

// ============================================================
// gemm0: mma.sync bf16-split GEMM.
// [y0|r0][128rows x 64] = Xtile[128x128] @ [wl0;wr0]^T
// A fragments loaded directly from global (float2) + converted in regs.
// W hi/lo staged in smem, stride 68 u32 (conflict-free fragment loads).
// ============================================================
#define BSTRIDE 68

__global__ __launch_bounds__(256) void gemm0_kernel(const float* __restrict__ x)
{
    __shared__ uint sbh[64 * BSTRIDE];
    __shared__ uint sbl[64 * BSTRIDE];

    int tid = threadIdx.x;
    int wid = tid >> 5, lane = tid & 31;

    // stage W: 4096 u32 each (64 rows x 64 u32)
    {
        const uint* whi = (const uint*)g_whi;
        const uint* wlo = (const uint*)g_wlo;
        #pragma unroll
        for (int c = tid; c < 4096; c += 256) {
            int r = c >> 6, k = c & 63;
            sbh[r * BSTRIDE + k] = __ldg(whi + c);
            sbl[r * BSTRIDE + k] = __ldg(wlo + c);
        }
    }
    __syncthreads();

    int mrow = lane >> 2;              // 0..7
    int c = lane & 3;                  // k-pair index
    int nl = lane >> 2;                // n within ntile

    int row0 = blockIdx.x * 128 + wid * 16 + mrow;
    const float2* x2 = (const float2*)x;
    size_t base0 = (size_t)row0 * 64 + c;          // float2 units
    size_t base1 = base0 + 8 * 64;                 // row0 + 8

    float d[8][4];
    #pragma unroll
    for (int n = 0; n < 8; n++)
        #pragma unroll
        for (int j = 0; j < 4; j++) d[n][j] = 0.f;

    #pragma unroll
    for (int ks = 0; ks < 8; ks++) {
        // ---- A fragments: 4 float2 loads, convert hi + residual lo ----
        float2 p0 = __ldg(&x2[base0 + ks * 8]);        // a0: row m,   k 2c
        float2 p1 = __ldg(&x2[base1 + ks * 8]);        // a1: row m+8, k 2c
        float2 p2 = __ldg(&x2[base0 + ks * 8 + 4]);    // a2: row m,   k 2c+8
        float2 p3 = __ldg(&x2[base1 + ks * 8 + 4]);    // a3: row m+8, k 2c+8

        uint ah[4], al[4];
        ah[0] = pkbf(p0.x, p0.y);
        ah[1] = pkbf(p1.x, p1.y);
        ah[2] = pkbf(p2.x, p2.y);
        ah[3] = pkbf(p3.x, p3.y);
        {
            __nv_bfloat162 h0 = *(__nv_bfloat162*)&ah[0];
            __nv_bfloat162 h1 = *(__nv_bfloat162*)&ah[1];
            __nv_bfloat162 h2 = *(__nv_bfloat162*)&ah[2];
            __nv_bfloat162 h3 = *(__nv_bfloat162*)&ah[3];
            al[0] = pkbf(p0.x - __bfloat162float(h0.x), p0.y - __bfloat162float(h0.y));
            al[1] = pkbf(p1.x - __bfloat162float(h1.x), p1.y - __bfloat162float(h1.y));
            al[2] = pkbf(p2.x - __bfloat162float(h2.x), p2.y - __bfloat162float(h2.y));
            al[3] = pkbf(p3.x - __bfloat162float(h3.x), p3.y - __bfloat162float(h3.y));
        }

        // ---- 8 n-tiles: B fragments from smem, 3 MMAs each ----
        #pragma unroll
        for (int n = 0; n < 8; n++) {
            int bidx = (n * 8 + nl) * BSTRIDE + ks * 8 + c;
            uint bh0 = sbh[bidx], bh1 = sbh[bidx + 4];
            uint bl0 = sbl[bidx], bl1 = sbl[bidx + 4];
            mma_bf16(d[n], ah, bh0, bh1);   // Xhi * Whi
            mma_bf16(d[n], al, bh0, bh1);   // Xlo * Whi
            mma_bf16(d[n], ah, bl0, bl1);   // Xhi * Wlo
        }
    }

    // ---- epilogue: ntiles 0-3 -> y0 cols, 4-7 -> r0 cols ----
    int rA = row0;           // rows lane/4
    int rB = row0 + 8;
    #pragma unroll
    for (int n = 0; n < 8; n++) {
        int col = (n & 3) * 8 + c * 2;
        if (n < 4) {
            *(float2*)(g_y0 + (size_t)rA * CH + col) = make_float2(d[n][0], d[n][1]);
            *(float2*)(g_y0 + (size_t)rB * CH + col) = make_float2(d[n][2], d[n][3]);
        } else if (rA < CN1) {
            *(float2*)(g_r0 + (size_t)rA * CH + col) = make_float2(d[n][0], d[n][1]);
            *(float2*)(g_r0 + (size_t)rB * CH + col) = make_float2(d[n][2], d[n][3]);
        }
    }
}

// ============================================================
// zero: cnt0 and cnt1 -> 0
// ============================================================
__global__ __launch_bounds__(256) void zero_kernel()
{
    int t = blockIdx.x * 256 + threadIdx.x;
    const int4 z = make_int4(0, 0, 0, 0);
    if (t < CN1 / 4) ((int4*)g_cnt0)[t] = z;
    else             ((int4*)g_cnt1)[t - CN1 / 4] = z;
}

// ============================================================
// hist / scanA / scanB / initcur / bucket  (CSR build)
// ============================================================
template <int LAYER>
__global__ __launch_bounds__(256) void hist_kernel(const int* __restrict__ tgt)
{
    int* cnt = (LAYER == 0) ? g_cnt0 : g_cnt1;
    int b = (blockIdx.x * 256 + threadIdx.x) * 4;
    int4 t = __ldg((const int4*)(tgt + b));
    atomicAdd(&cnt[t.x], 1);
    atomicAdd(&cnt[t.y], 1);
    atomicAdd(&cnt[t.z], 1);
    atomicAdd(&cnt[t.w], 1);
}

template <int LAYER>
__global__ __launch_bounds__(256) void scanA_kernel()
{
    const int* cnt = (LAYER == 0) ? g_cnt0 : g_cnt1;
    int* offl = (LAYER == 0) ? g_offl0 : g_offl1;
    int* part = (LAYER == 0) ? g_part0 : g_part1;

    __shared__ int wsum[8];
    int tid = threadIdx.x;
    int base = blockIdx.x * 1024 + tid * 4;
    int4 c = __ldg((const int4*)(cnt + base));
    int s1 = c.x + c.y, s2 = s1 + c.z, s3 = s2 + c.w;

    int lane = tid & 31, w = tid >> 5;
    int v = s3;
    #pragma unroll
    for (int o = 1; o < 32; o <<= 1) {
        int t = __shfl_up_sync(0xffffffffu, v, o);
        if (lane >= o) v += t;
    }
    int thr_excl = v - s3;
    if (lane == 31) wsum[w] = v;
    __syncthreads();
    if (w == 0) {
        int ws = (lane < 8) ? wsum[lane] : 0;
        #pragma unroll
        for (int o = 1; o < 8; o <<= 1) {
            int t = __shfl_up_sync(0xffffffffu, ws, o);
            if (lane >= o) ws += t;
        }
        if (lane < 8) wsum[lane] = ws;
    }
    __syncthreads();
    int wexcl = (w == 0) ? 0 : wsum[w - 1];
    int e = wexcl + thr_excl;

    int4 o4;
    o4.x = e; o4.y = e + c.x; o4.z = e + s1; o4.w = e + s2;
    *(int4*)(offl + base) = o4;
    if (tid == 255) part[blockIdx.x] = wsum[7];
}

template <int LAYER>
__global__ __launch_bounds__(128) void scanB_kernel()
{
    int* part = (LAYER == 0) ? g_part0 : g_part1;
    const int n = (LAYER == 0) ? (CN1 / 1024) : (CN2 / 1024);

    __shared__ int ws[4];
    int tid = threadIdx.x;
    int v = (tid < n) ? part[tid] : 0;
    int lane = tid & 31, w = tid >> 5;
    int x = v;
    #pragma unroll
    for (int o = 1; o < 32; o <<= 1) {
        int t = __shfl_up_sync(0xffffffffu, x, o);
        if (lane >= o) x += t;
    }
    if (lane == 31) ws[w] = x;
    __syncthreads();
    if (tid == 0) {
        int a = 0;
        #pragma unroll
        for (int i = 0; i < 4; i++) { int t = ws[i]; ws[i] = a; a += t; }
    }
    __syncthreads();
    if (tid < n) part[tid] = (x - v) + ws[w];
}

template <int LAYER>
__global__ __launch_bounds__(256) void initcur_kernel()
{
    const int* offl = (LAYER == 0) ? g_offl0 : g_offl1;
    const int* part = (LAYER == 0) ? g_part0 : g_part1;
    int* cur = (LAYER == 0) ? g_cur0 : g_cur1;
    int i = blockIdx.x * 256 + threadIdx.x;
    cur[i] = offl[i] + part[i >> 10];
}

template <int LAYER>
__global__ __launch_bounds__(256) void bucket_kernel(
    const int* __restrict__ src, const int* __restrict__ tgt)
{
    int* cur = (LAYER == 0) ? g_cur0 : g_cur1;
    int* eid = (LAYER == 0) ? g_eid0 : g_eid1;

    int b = (blockIdx.x * 256 + threadIdx.x) * 4;
    int4 t = __ldg((const int4*)(tgt + b));
    int4 s = __ldg((const int4*)(src + b));
    #pragma unroll
    for (int i = 0; i < 4; i++) {
        int ti = (i == 0) ? t.x : (i == 1) ? t.y : (i == 2) ? t.z : t.w;
        int si = (i == 0) ? s.x : (i == 1) ? s.y : (i == 2) ? s.z : s.w;
        int pos = atomicAdd(&cur[ti], 1);
        eid[pos] = si;
    }
}

// ============================================================
// aggfin: warp per target row; gather + fused finalize.
// ============================================================
template <int LAYER>
__global__ __launch_bounds__(256) void aggfin_kernel(
    const float* __restrict__ bias, float* __restrict__ out_param)
{
    const float* table = (LAYER == 0) ? g_y0 : g_z1;
    const float* rt    = (LAYER == 0) ? g_r0 : g_r1;
    const int*   cnta  = (LAYER == 0) ? g_cnt0 : g_cnt1;
    const int*   cura  = (LAYER == 0) ? g_cur0 : g_cur1;   // = end offset
    const int*   eid   = (LAYER == 0) ? g_eid0 : g_eid1;
    float*       out   = (LAYER == 0) ? g_h : out_param;

    int lane = threadIdx.x & 31;
    int row = blockIdx.x * 8 + (threadIdx.x >> 5);
    int g = lane >> 3;
    int f4 = lane & 7;

    int cnt = __ldg(cnta + row);
    int start = __ldg(cura + row) - cnt;

    float4 acc = make_float4(0.f, 0.f, 0.f, 0.f);
    for (int i = g; i < cnt; i += 4) {
        int s = __ldg(eid + start + i);
        float4 v = __ldg((const float4*)(table + (size_t)s * CH) + f4);
        acc.x += v.x; acc.y += v.y; acc.z += v.z; acc.w += v.w;
    }
    #pragma unroll
    for (int o = 8; o <= 16; o <<= 1) {
        acc.x += __shfl_xor_sync(0xffffffffu, acc.x, o);
        acc.y += __shfl_xor_sync(0xffffffffu, acc.y, o);
        acc.z += __shfl_xor_sync(0xffffffffu, acc.z, o);
        acc.w += __shfl_xor_sync(0xffffffffu, acc.w, o);
    }

    float inv = 1.f / (float)max(cnt, 1);
    float4 b = __ldg((const float4*)bias + f4);
    float4 r = __ldg((const float4*)(rt + (size_t)row * CH) + f4);

    float4 v;
    v.x = fmaf(acc.x, inv, b.x) + r.x;
    v.y = fmaf(acc.y, inv, b.y) + r.y;
    v.z = fmaf(acc.z, inv, b.z) + r.z;
    v.w = fmaf(acc.w, inv, b.w) + r.w;

    float s = v.x * v.x + v.y * v.y + v.z * v.z + v.w * v.w;
    s += __shfl_xor_sync(0xffffffffu, s, 1);
    s += __shfl_xor_sync(0xffffffffu, s, 2);
    s += __shfl_xor_sync(0xffffffffu, s, 4);
    float rinv = 1.f / fmaxf(sqrtf(s), CEPS);

    float4 o;
    o.x = v.x * rinv; o.y = v.y * rinv; o.z = v.z * rinv; o.w = v.w * rinv;
    if (LAYER == 0) {
        o.x = fmaxf(o.x, 0.f); o.y = fmaxf(o.y, 0.f);
        o.z = fmaxf(o.z, 0.f); o.w = fmaxf(o.w, 0.f);
    }
    if (g == 0)
        ((float4*)(out + (size_t)row * CH))[f4] = o;
}

// ============================================================
// proj1: z1 = h@wl1^T (all N1), r1 = h[:N2]@wr1^T. (SIMT)
// ============================================================
__global__ __launch_bounds__(256) void proj1_kernel(
    const float* __restrict__ wl1, const float* __restrict__ wr1)
{
    __shared__ float swl[CH * CH];
    __shared__ float swr[CH * CH];
    int tid = threadIdx.x;
    for (int idx = tid; idx < CH * CH; idx += 256) {
        int j = idx >> 5, k = idx & 31;
        swl[k * CH + j] = wl1[idx];
        swr[k * CH + j] = wr1[idx];
    }
    __syncthreads();

    int lane = tid & 31;
    int warp = blockIdx.x * 8 + (tid >> 5);
    int rb = warp * 4;

    const float4* h4 = (const float4*)g_h;
    size_t b0 = (size_t)rb * 8;

    float al[4] = {0.f, 0.f, 0.f, 0.f};
    float ar[4] = {0.f, 0.f, 0.f, 0.f};

    #pragma unroll
    for (int k4 = 0; k4 < 8; k4++) {
        float4 v[4];
        #pragma unroll
        for (int i = 0; i < 4; i++) v[i] = h4[b0 + (size_t)i * 8 + k4];
        int kb = k4 * 4;
        float wlr[4], wrr[4];
        #pragma unroll
        for (int d = 0; d < 4; d++) {
            wlr[d] = swl[(kb + d) * CH + lane];
            wrr[d] = swr[(kb + d) * CH + lane];
        }
        #pragma unroll
        for (int i = 0; i < 4; i++) {
            al[i] = fmaf(v[i].x, wlr[0], al[i]);
            al[i] = fmaf(v[i].y, wlr[1], al[i]);
            al[i] = fmaf(v[i].z, wlr[2], al[i]);
            al[i] = fmaf(v[i].w, wlr[3], al[i]);
            ar[i] = fmaf(v[i].x, wrr[0], ar[i]);
            ar[i] = fmaf(v[i].y, wrr[1], ar[i]);
            ar[i] = fmaf(v[i].z, wrr[2], ar[i]);
            ar[i] = fmaf(v[i].w, wrr[3], ar[i]);
        }
    }

    #pragma unroll
    for (int i = 0; i < 4; i++) {
        int r = rb + i;
        g_z1[(size_t)r * CH + lane] = al[i];
        if (r < CN2) g_r1[(size_t)r * CH + lane] = ar[i];
    }
}

// ============================================================
extern "C" void kernel_launch(void* const* d_in, const int* in_sizes, int n_in,
                              void* d_out, int out_size)
{
    const float* x    = (const float*)d_in[0];
    const int*   src0 = (const int*)d_in[1];
    const int*   tgt0 = (const int*)d_in[2];
    const int*   src1 = (const int*)d_in[3];
    const int*   tgt1 = (const int*)d_in[4];
    const float* wl0  = (const float*)d_in[5];
    const float* bl0  = (const float*)d_in[6];
    const float* wr0  = (const float*)d_in[7];
    const float* wl1  = (const float*)d_in[8];
    const float* bl1  = (const float*)d_in[9];
    const float* wr1  = (const float*)d_in[10];
    float* out = (float*)d_out;

    prep_w_kernel<<<64 * CIN / 256, 256>>>(wl0, wr0);           // 0
    zero_kernel<<<(CN1 / 4 + CN2 / 4) / 256, 256>>>();          // 1
    hist_kernel<0><<<CE0 / 1024, 256>>>(tgt0);                  // 2
    gemm0_kernel<<<CN0 / 128, 256>>>(x);                        // 3  <- ncu capture
    scanA_kernel<0><<<CN1 / 1024, 256>>>();                     // 4
    scanB_kernel<0><<<1, 128>>>();                              // 5
    initcur_kernel<0><<<CN1 / 256, 256>>>();                    // 6
    bucket_kernel<0><<<CE0 / 1024, 256>>>(src0, tgt0);          // 7
    aggfin_kernel<0><<<CN1 / 8, 256>>>(bl0, nullptr);           // 8
    proj1_kernel<<<CN1 / 32, 256>>>(wl1, wr1);                  // 9
    hist_kernel<1><<<CE1 / 1024, 256>>>(tgt1);                  // 10
    scanA_kernel<1><<<CN2 / 1024, 256>>>();                     // 11
    scanB_kernel<1><<<1, 128>>>();                              // 12
    initcur_kernel<1><<<CN2 / 256, 256>>>();                    // 13
    bucket_kernel<1><<<CE1 / 1024, 256>>>(src1, tgt1);          // 14
    aggfin_kernel<1><<<CN2 / 8, 256>>>(bl1, out);               // 15
}